// round 3
// baseline (speedup 1.0000x reference)
#include <cuda_runtime.h>
#include <math.h>

// FusionHead fused kernel, R2: 4-features-per-thread + packed f32x2 FMA.
// D=192, H=3, HD=64, FFN hidden 384, fingerprint 128. B rows, 16 rows/block.
//
// Output layout: out[c*B + i] (c=0..2 sigmoid probs), out[3B + i*128 + f] fp.

#define D    192
#define HD   64
#define FPD  128
#define RPB  16          // rows per block
#define NT   192         // threads per block
#define RT   32          // row-tokens per block = 2*RPB

// smem layout (floats)
#define OFF_SEQ   0                      // [32][192]  seq -> x (in place)
#define OFF_QKV   (RT * D)               // [32][576]  staging / qkv / ctx / h / heads
#define OFF_SC    (OFF_QKV + RT * 3 * D) // [16][12]   attention scores
#define OFF_MU    (OFF_SC + RPB * 12)    // [32]
#define OFF_RSTD  (OFF_MU + RT)          // [32]
#define OFF_INV   (OFF_RSTD + RT)        // [16]
#define SMEM_FLOATS (OFF_INV + RPB)
#define SMEM_BYTES  (SMEM_FLOATS * 4)

typedef unsigned long long u64t;

static __device__ __forceinline__ float4 ldf4(const float* p) {
    return *reinterpret_cast<const float4*>(p);
}

// packed f32x2 fma: d.lo = a.lo*b.lo + c.lo ; d.hi = a.hi*b.hi + c.hi
static __device__ __forceinline__ u64t fma2(u64t a, u64t b, u64t c) {
    u64t d;
    asm("fma.rn.f32x2 %0, %1, %2, %3;" : "=l"(d) : "l"(a), "l"(b), "l"(c));
    return d;
}
static __device__ __forceinline__ float hsum2(u64t a) {
    unsigned lo, hi;
    asm("mov.b64 {%0,%1}, %2;" : "=r"(lo), "=r"(hi) : "l"(a));
    return __uint_as_float(lo) + __uint_as_float(hi);
}

// GEMM tile: this thread computes 4 consecutive output features (f0..f0+3)
// for NRG consecutive rows. Weights LDG.128, activations LDS.128 (reused
// across the 4 features), math in packed f32x2.
// EPI: 0 = store, 1 = relu-store, 2 = add-into (residual, bias included).
template<int NRG, int EPI>
static __device__ __forceinline__ void gemm4(
    const float* __restrict__ W, int ldw, int K,
    const float* __restrict__ bias,
    const float* __restrict__ sin, int sstride,   // thread's first input row
    float* __restrict__ outp, int ostride,        // &out[row0][f0]
    int f0)
{
    u64t acc[4][NRG];
#pragma unroll
    for (int j = 0; j < 4; j++)
#pragma unroll
        for (int r = 0; r < NRG; r++) acc[j][r] = 0ull;

    const float* w0 = W + (size_t)f0 * ldw;
#pragma unroll 2
    for (int k = 0; k < K; k += 4) {
        ulonglong2 wv0 = *reinterpret_cast<const ulonglong2*>(w0 + 0 * ldw + k);
        ulonglong2 wv1 = *reinterpret_cast<const ulonglong2*>(w0 + 1 * ldw + k);
        ulonglong2 wv2 = *reinterpret_cast<const ulonglong2*>(w0 + 2 * ldw + k);
        ulonglong2 wv3 = *reinterpret_cast<const ulonglong2*>(w0 + 3 * ldw + k);
#pragma unroll
        for (int r = 0; r < NRG; r++) {
            ulonglong2 av = *reinterpret_cast<const ulonglong2*>(sin + r * sstride + k);
            acc[0][r] = fma2(wv0.x, av.x, acc[0][r]);
            acc[0][r] = fma2(wv0.y, av.y, acc[0][r]);
            acc[1][r] = fma2(wv1.x, av.x, acc[1][r]);
            acc[1][r] = fma2(wv1.y, av.y, acc[1][r]);
            acc[2][r] = fma2(wv2.x, av.x, acc[2][r]);
            acc[2][r] = fma2(wv2.y, av.y, acc[2][r]);
            acc[3][r] = fma2(wv3.x, av.x, acc[3][r]);
            acc[3][r] = fma2(wv3.y, av.y, acc[3][r]);
        }
    }
    const float4 bv = ldf4(bias + f0);
#pragma unroll
    for (int r = 0; r < NRG; r++) {
        float4 res;
        res.x = hsum2(acc[0][r]) + bv.x;
        res.y = hsum2(acc[1][r]) + bv.y;
        res.z = hsum2(acc[2][r]) + bv.z;
        res.w = hsum2(acc[3][r]) + bv.w;
        float* op = outp + r * ostride;
        if (EPI == 1) {
            res.x = fmaxf(res.x, 0.f); res.y = fmaxf(res.y, 0.f);
            res.z = fmaxf(res.z, 0.f); res.w = fmaxf(res.w, 0.f);
        }
        if (EPI == 2) {
            float4 o = ldf4(op);
            res.x += o.x; res.y += o.y; res.z += o.z; res.w += o.w;
        }
        *reinterpret_cast<float4*>(op) = res;
    }
}

// In-place LayerNorm over last dim (192) for 32 row-tokens in sSeq.
static __device__ __forceinline__ void block_layernorm(
    float* __restrict__ sSeq, float* __restrict__ sMu, float* __restrict__ sRstd,
    const float* __restrict__ g, const float* __restrict__ b, int tid)
{
    const int wid = tid >> 5, lane = tid & 31;
    for (int rt = wid; rt < RT; rt += NT / 32) {
        float s = 0.f, s2 = 0.f;
#pragma unroll
        for (int i = lane; i < D; i += 32) {
            float v = sSeq[rt * D + i];
            s += v;
            s2 = fmaf(v, v, s2);
        }
#pragma unroll
        for (int o = 16; o > 0; o >>= 1) {
            s  += __shfl_xor_sync(0xFFFFFFFFu, s, o);
            s2 += __shfl_xor_sync(0xFFFFFFFFu, s2, o);
        }
        if (lane == 0) {
            float mu  = s * (1.f / D);
            float var = s2 * (1.f / D) - mu * mu;
            sMu[rt]   = mu;
            sRstd[rt] = rsqrtf(var + 1e-5f);
        }
    }
    __syncthreads();
    const float gg = g[tid], bb = b[tid];
#pragma unroll 4
    for (int rt = 0; rt < RT; rt++) {
        float v = sSeq[rt * D + tid];
        sSeq[rt * D + tid] = (v - sMu[rt]) * sRstd[rt] * gg + bb;
    }
    __syncthreads();
}

__global__ void __launch_bounds__(NT, 2)
fusion_head_kernel(
    const float* __restrict__ perc, const float* __restrict__ tech,
    const float* __restrict__ Wp,   const float* __restrict__ bp,
    const float* __restrict__ Wt,   const float* __restrict__ bt,
    const float* __restrict__ in_w, const float* __restrict__ in_b,
    const float* __restrict__ out_w,const float* __restrict__ out_b,
    const float* __restrict__ w1,   const float* __restrict__ b1,
    const float* __restrict__ w2,   const float* __restrict__ b2,
    const float* __restrict__ ln1g, const float* __restrict__ ln1b,
    const float* __restrict__ ln2g, const float* __restrict__ ln2b,
    const float* __restrict__ cw1,  const float* __restrict__ cb1,
    const float* __restrict__ cw2,  const float* __restrict__ cb2,
    const float* __restrict__ fw,   const float* __restrict__ fb,
    float* __restrict__ out, int B)
{
    extern __shared__ float sm[];
    float* sSeq  = sm + OFF_SEQ;   // [32][192]
    float* sQKV  = sm + OFF_QKV;   // [32][576]
    float* sSc   = sm + OFF_SC;
    float* sMu   = sm + OFF_MU;
    float* sRstd = sm + OFF_RSTD;
    float* sInv  = sm + OFF_INV;

    const int tid = threadIdx.x;
    const int fg  = tid % 48;      // feature group (4 features)
    const int rg  = tid / 48;      // row group (0..3)
    const int f0  = fg * 4;
    const int r0  = blockIdx.x * RPB;

    // ---------- stage perc rows into sQKV rows (stride 576), compute p ----------
#pragma unroll
    for (int r = 0; r < RPB; r++) {
        int gr = r0 + r; if (gr >= B) gr = B - 1;
        sQKV[r * 576 + tid] = perc[(size_t)gr * D + tid];
    }
    __syncthreads();
    gemm4<4, 0>(Wp, D, D, bp, sQKV + rg * 4 * 576, 576,
                sSeq + (rg * 8) * D + f0, 2 * D, f0);
    __syncthreads();

    // ---------- stage tech rows, compute t ----------
#pragma unroll
    for (int r = 0; r < RPB; r++) {
        int gr = r0 + r; if (gr >= B) gr = B - 1;
        sQKV[r * 576 + tid] = tech[(size_t)gr * D + tid];
    }
    __syncthreads();
    gemm4<4, 0>(Wt, D, D, bt, sQKV + rg * 4 * 576, 576,
                sSeq + (rg * 8 + 1) * D + f0, 2 * D, f0);
    __syncthreads();

    // ---------- qkv = seq @ in_w^T + in_b  (3 passes) ----------
    for (int m = 0; m < 3; m++) {
        gemm4<8, 0>(in_w + (size_t)m * D * D, D, D, in_b + m * D,
                    sSeq + rg * 8 * D, D,
                    sQKV + rg * 8 * 576 + m * D + f0, 576, f0);
    }
    __syncthreads();

    // ---------- attention scores: one 64-dot per thread ----------
    {
        const int r   = tid / 12;
        const int idx = tid % 12;
        const int h = idx >> 2, qt = (idx >> 1) & 1, kt = idx & 1;
        const float* q  = &sQKV[(2 * r + qt) * 576 + h * HD];
        const float* kk = &sQKV[(2 * r + kt) * 576 + D + h * HD];
        float s = 0.f;
#pragma unroll
        for (int d = 0; d < HD; d += 4) {
            float4 qa = ldf4(q + d), ka = ldf4(kk + d);
            s = fmaf(qa.x, ka.x, s);
            s = fmaf(qa.y, ka.y, s);
            s = fmaf(qa.z, ka.z, s);
            s = fmaf(qa.w, ka.w, s);
        }
        sSc[tid] = s * 0.125f;   // 1/sqrt(64)
    }
    __syncthreads();

    // ---------- softmax + ctx (overwrites q slots, cols [0,192)) ----------
    {
        const int h = tid >> 6;
#pragma unroll 2
        for (int r = 0; r < RPB; r++) {
            const float v0 = sQKV[(2 * r)     * 576 + 2 * D + tid];
            const float v1 = sQKV[(2 * r + 1) * 576 + 2 * D + tid];
            const float* sc = &sSc[r * 12 + h * 4];
            float ctx0, ctx1;
            {
                float s0 = sc[0], s1 = sc[1];
                float mx = fmaxf(s0, s1);
                float e0 = __expf(s0 - mx), e1 = __expf(s1 - mx);
                ctx0 = (e0 * v0 + e1 * v1) / (e0 + e1);
            }
            {
                float s0 = sc[2], s1 = sc[3];
                float mx = fmaxf(s0, s1);
                float e0 = __expf(s0 - mx), e1 = __expf(s1 - mx);
                ctx1 = (e0 * v0 + e1 * v1) / (e0 + e1);
            }
            sQKV[(2 * r)     * 576 + tid] = ctx0;
            sQKV[(2 * r + 1) * 576 + tid] = ctx1;
        }
    }
    __syncthreads();

    // ---------- attn out-proj, residual-add into sSeq ----------
    gemm4<8, 2>(out_w, D, D, out_b, sQKV + rg * 8 * 576, 576,
                sSeq + rg * 8 * D + f0, D, f0);
    __syncthreads();

    // ---------- LN1 ----------
    block_layernorm(sSeq, sMu, sRstd, ln1g, ln1b, tid);

    // ---------- FFN1: relu(x @ w1^T + b1) -> sQKV cols [0,384) ----------
    for (int m = 0; m < 2; m++) {
        gemm4<8, 1>(w1 + (size_t)m * D * D, D, D, b1 + m * D,
                    sSeq + rg * 8 * D, D,
                    sQKV + rg * 8 * 576 + m * D + f0, 576, f0);
    }
    __syncthreads();

    // ---------- FFN2 (K=384), residual-add into sSeq ----------
    gemm4<8, 2>(w2, 2 * D, 2 * D, b2, sQKV + rg * 8 * 576, 576,
                sSeq + rg * 8 * D + f0, D, f0);
    __syncthreads();

    // ---------- LN2 ----------
    block_layernorm(sSeq, sMu, sRstd, ln2g, ln2b, tid);

    // ---------- pooled z into sSeq rows [0,16) ----------
#pragma unroll
    for (int r = 0; r < RPB; r++) {
        float z = 0.5f * (sSeq[(2 * r) * D + tid] + sSeq[(2 * r + 1) * D + tid]);
        sSeq[r * D + tid] = z;
    }
    __syncthreads();

    // ---------- classifier hidden -> sQKV rows [0,16) ----------
    gemm4<4, 1>(cw1, D, D, cb1, sSeq + rg * 4 * D, D,
                sQKV + rg * 4 * 576 + f0, 576, f0);

    // ---------- fingerprint -> sQKV rows [16,32), 128 features ----------
    if (fg < 32) {
        gemm4<4, 0>(fw, D, D, fb, sSeq + rg * 4 * D, D,
                    sQKV + (RPB + rg * 4) * 576 + f0, 576, f0);
    }
    __syncthreads();

    // ---------- logits + sigmoid ----------
    if (tid < 3 * RPB) {
        const int r = tid / 3, c = tid % 3;
        const float* y = &sQKV[r * 576];
        const float* w = cw2 + c * D;
        float s = cb2[c];
#pragma unroll
        for (int k = 0; k < D; k += 4) {
            float4 ya = ldf4(y + k), wa = ldf4(w + k);
            s = fmaf(ya.x, wa.x, s);
            s = fmaf(ya.y, wa.y, s);
            s = fmaf(ya.z, wa.z, s);
            s = fmaf(ya.w, wa.w, s);
        }
        const int gr = r0 + r;
        if (gr < B) out[(size_t)c * B + gr] = 1.f / (1.f + __expf(-s));
    }

    // ---------- fingerprint norm ----------
    if (tid < RPB) {
        const float* fpv = &sQKV[(RPB + tid) * 576];
        float ss = 0.f;
#pragma unroll 4
        for (int i = 0; i < FPD; i++) ss = fmaf(fpv[i], fpv[i], ss);
        sInv[tid] = 1.f / fmaxf(sqrtf(ss), 1e-12f);
    }
    __syncthreads();
    if (tid < FPD) {
#pragma unroll
        for (int r = 0; r < RPB; r++) {
            const int gr = r0 + r;
            if (gr < B)
                out[(size_t)3 * B + (size_t)gr * FPD + tid] =
                    sQKV[(RPB + r) * 576 + tid] * sInv[r];
        }
    }
}

extern "C" void kernel_launch(void* const* d_in, const int* in_sizes, int n_in,
                              void* d_out, int out_size)
{
    (void)n_in; (void)out_size;
    const float* perc = (const float*)d_in[0];
    const float* tech = (const float*)d_in[1];
    const float* Wp   = (const float*)d_in[2];
    const float* bp   = (const float*)d_in[3];
    const float* Wt   = (const float*)d_in[4];
    const float* bt   = (const float*)d_in[5];
    const float* in_w = (const float*)d_in[6];
    const float* in_b = (const float*)d_in[7];
    const float* outw = (const float*)d_in[8];
    const float* outb = (const float*)d_in[9];
    const float* w1   = (const float*)d_in[10];
    const float* b1   = (const float*)d_in[11];
    const float* w2   = (const float*)d_in[12];
    const float* b2   = (const float*)d_in[13];
    const float* ln1g = (const float*)d_in[14];
    const float* ln1b = (const float*)d_in[15];
    const float* ln2g = (const float*)d_in[16];
    const float* ln2b = (const float*)d_in[17];
    const float* cw1  = (const float*)d_in[18];
    const float* cb1  = (const float*)d_in[19];
    const float* cw2  = (const float*)d_in[20];
    const float* cb2  = (const float*)d_in[21];
    const float* fw   = (const float*)d_in[22];
    const float* fb   = (const float*)d_in[23];

    const int B = in_sizes[0] / D;
    const int grid = (B + RPB - 1) / RPB;

    cudaFuncSetAttribute(fusion_head_kernel,
                         cudaFuncAttributeMaxDynamicSharedMemorySize, SMEM_BYTES);

    fusion_head_kernel<<<grid, NT, SMEM_BYTES>>>(
        perc, tech, Wp, bp, Wt, bt, in_w, in_b, outw, outb,
        w1, b1, w2, b2, ln1g, ln1b, ln2g, ln2b,
        cw1, cb1, cw2, cb2, fw, fb, (float*)d_out, B);
}

// round 10
// speedup vs baseline: 2.8058x; 2.8058x over previous
#include <cuda_runtime.h>
#include <math.h>

// FusionHead fused kernel, R4: transposed weights (coalesced LDG) +
// f32x2 packed over K (no splats) + 4 features x 8 rows per thread.
// D=192, H=3, HD=64, FFN hidden 384, fingerprint 128. 16 rows/block.
//
// Output layout: out[c*B + i] (c=0..2 sigmoid probs), out[3B + i*128 + f] fp.

#define D    192
#define HD   64
#define FPD  128
#define RPB  16          // rows per block
#define NT   192         // threads per block
#define RT   32          // row-tokens per block = 2*RPB

// smem layout (floats)
#define OFF_SEQ   0                      // [32][192]  seq -> x (in place)
#define OFF_QKV   (RT * D)               // [32][576]  staging / qkv / ctx / h / heads
#define OFF_SC    (OFF_QKV + RT * 3 * D) // [16][12]   attention scores
#define OFF_MU    (OFF_SC + RPB * 12)    // [32]
#define OFF_RSTD  (OFF_MU + RT)          // [32]
#define OFF_INV   (OFF_RSTD + RT)        // [16]
#define SMEM_FLOATS (OFF_INV + RPB)
#define SMEM_BYTES  (SMEM_FLOATS * 4)

// ---- transposed-weight arena (floats). WT layout: [K][N] row-major ----
#define T_WP   0                               // [192][192]
#define T_WT   (T_WP  + 192 * 192)             // [192][192]
#define T_IN   (T_WT  + 192 * 192)             // [192][576]
#define T_OUT  (T_IN  + 192 * 576)             // [192][192]
#define T_W1   (T_OUT + 192 * 192)             // [192][384]
#define T_W2   (T_W1  + 192 * 384)             // [384][192]
#define T_CW1  (T_W2  + 384 * 192)             // [192][192]
#define T_FW   (T_CW1 + 192 * 192)             // [192][128]
#define T_TOTAL (T_FW + 192 * 128)             // 430080 floats = 1.72MB

__device__ __align__(16) float g_wt[T_TOTAL];

typedef unsigned long long u64t;

static __device__ __forceinline__ float4 ldf4(const float* p) {
    return *reinterpret_cast<const float4*>(p);
}
// packed f32x2 fma: d.lo = a.lo*b.lo + c.lo ; d.hi = a.hi*b.hi + c.hi
static __device__ __forceinline__ u64t fma2(u64t a, u64t b, u64t c) {
    u64t d;
    asm("fma.rn.f32x2 %0, %1, %2, %3;" : "=l"(d) : "l"(a), "l"(b), "l"(c));
    return d;
}
static __device__ __forceinline__ u64t pack2(float lo, float hi) {
    u64t d;
    asm("mov.b64 %0, {%1, %2};" : "=l"(d) : "f"(lo), "f"(hi));
    return d;
}
static __device__ __forceinline__ float hsum2(u64t a) {
    unsigned lo, hi;
    asm("mov.b64 {%0,%1}, %2;" : "=r"(lo), "=r"(hi) : "l"(a));
    return __uint_as_float(lo) + __uint_as_float(hi);
}

// ---- transpose pre-kernel: dst[k*N+f] = src[f*K+k], src is [N_out][K_in] ----
__global__ void transpose_weights(
    const float* __restrict__ Wp,   const float* __restrict__ Wt,
    const float* __restrict__ in_w, const float* __restrict__ out_w,
    const float* __restrict__ w1,   const float* __restrict__ w2,
    const float* __restrict__ cw1,  const float* __restrict__ fw)
{
    const float* src; float* dst; int K, N;   // src [N][K] -> dst [K][N]
    switch (blockIdx.y) {
        case 0:  src = Wp;   dst = g_wt + T_WP;  K = 192; N = 192; break;
        case 1:  src = Wt;   dst = g_wt + T_WT;  K = 192; N = 192; break;
        case 2:  src = in_w; dst = g_wt + T_IN;  K = 192; N = 576; break;
        case 3:  src = out_w;dst = g_wt + T_OUT; K = 192; N = 192; break;
        case 4:  src = w1;   dst = g_wt + T_W1;  K = 192; N = 384; break;
        case 5:  src = w2;   dst = g_wt + T_W2;  K = 384; N = 192; break;
        case 6:  src = cw1;  dst = g_wt + T_CW1; K = 192; N = 192; break;
        default: src = fw;   dst = g_wt + T_FW;  K = 192; N = 128; break;
    }
    int idx = blockIdx.x * blockDim.x + threadIdx.x;
    if (idx < K * N) {
        int k = idx / N, f = idx % N;
        dst[idx] = src[f * K + k];   // coalesced writes
    }
}

// GEMM tile: 4 consecutive output features (f0..f0+3) x NRG rows.
// wcol = WT + f0 (WT is [K][ldwt]); weight float4 loads are lane-coalesced.
// Activations LDS.128 give ready-packed f32x2 pairs over K. Accumulators hold
// (even-k, odd-k) partial sums; reduced at epilogue.
// EPI: 0 = store, 1 = relu-store, 2 = add-into (residual).
template<int NRG, int EPI>
static __device__ __forceinline__ void gemm4t(
    const float* __restrict__ wcol, int ldwt, int K,
    const float* __restrict__ bias,
    const float* __restrict__ sin, int sstride,
    float* __restrict__ outp, int ostride,
    int f0)
{
    u64t acc[4][NRG];
#pragma unroll
    for (int j = 0; j < 4; j++)
#pragma unroll
        for (int r = 0; r < NRG; r++) acc[j][r] = 0ull;

    const float* wp = wcol;
#pragma unroll 2
    for (int k = 0; k < K; k += 4) {
        const float4 wk0 = ldf4(wp);
        const float4 wk1 = ldf4(wp + ldwt);
        const float4 wk2 = ldf4(wp + 2 * ldwt);
        const float4 wk3 = ldf4(wp + 3 * ldwt);
        wp += 4 * ldwt;
        u64t w01[4], w23[4];
        w01[0] = pack2(wk0.x, wk1.x); w01[1] = pack2(wk0.y, wk1.y);
        w01[2] = pack2(wk0.z, wk1.z); w01[3] = pack2(wk0.w, wk1.w);
        w23[0] = pack2(wk2.x, wk3.x); w23[1] = pack2(wk2.y, wk3.y);
        w23[2] = pack2(wk2.z, wk3.z); w23[3] = pack2(wk2.w, wk3.w);
#pragma unroll
        for (int r = 0; r < NRG; r++) {
            const ulonglong2 av = *reinterpret_cast<const ulonglong2*>(sin + r * sstride + k);
#pragma unroll
            for (int j = 0; j < 4; j++) {
                acc[j][r] = fma2(w01[j], av.x, acc[j][r]);
                acc[j][r] = fma2(w23[j], av.y, acc[j][r]);
            }
        }
    }
    const float4 bv = ldf4(bias + f0);
#pragma unroll
    for (int r = 0; r < NRG; r++) {
        float4 res;
        res.x = hsum2(acc[0][r]) + bv.x;
        res.y = hsum2(acc[1][r]) + bv.y;
        res.z = hsum2(acc[2][r]) + bv.z;
        res.w = hsum2(acc[3][r]) + bv.w;
        float* op = outp + r * ostride;
        if (EPI == 1) {
            res.x = fmaxf(res.x, 0.f); res.y = fmaxf(res.y, 0.f);
            res.z = fmaxf(res.z, 0.f); res.w = fmaxf(res.w, 0.f);
        }
        if (EPI == 2) {
            float4 o = ldf4(op);
            res.x += o.x; res.y += o.y; res.z += o.z; res.w += o.w;
        }
        *reinterpret_cast<float4*>(op) = res;
    }
}

// In-place LayerNorm over last dim (192) for 32 row-tokens in sSeq.
static __device__ __forceinline__ void block_layernorm(
    float* __restrict__ sSeq, float* __restrict__ sMu, float* __restrict__ sRstd,
    const float* __restrict__ g, const float* __restrict__ b, int tid)
{
    const int wid = tid >> 5, lane = tid & 31;
    for (int rt = wid; rt < RT; rt += NT / 32) {
        float s = 0.f, s2 = 0.f;
#pragma unroll
        for (int i = lane; i < D; i += 32) {
            float v = sSeq[rt * D + i];
            s += v;
            s2 = fmaf(v, v, s2);
        }
#pragma unroll
        for (int o = 16; o > 0; o >>= 1) {
            s  += __shfl_xor_sync(0xFFFFFFFFu, s, o);
            s2 += __shfl_xor_sync(0xFFFFFFFFu, s2, o);
        }
        if (lane == 0) {
            float mu  = s * (1.f / D);
            float var = s2 * (1.f / D) - mu * mu;
            sMu[rt]   = mu;
            sRstd[rt] = rsqrtf(var + 1e-5f);
        }
    }
    __syncthreads();
    const float gg = g[tid], bb = b[tid];
#pragma unroll 4
    for (int rt = 0; rt < RT; rt++) {
        float v = sSeq[rt * D + tid];
        sSeq[rt * D + tid] = (v - sMu[rt]) * sRstd[rt] * gg + bb;
    }
    __syncthreads();
}

__global__ void __launch_bounds__(NT, 2)
fusion_head_kernel(
    const float* __restrict__ perc, const float* __restrict__ tech,
    const float* __restrict__ bp,   const float* __restrict__ bt,
    const float* __restrict__ in_b, const float* __restrict__ out_b,
    const float* __restrict__ b1,   const float* __restrict__ b2,
    const float* __restrict__ ln1g, const float* __restrict__ ln1b,
    const float* __restrict__ ln2g, const float* __restrict__ ln2b,
    const float* __restrict__ cb1,
    const float* __restrict__ cw2,  const float* __restrict__ cb2,
    const float* __restrict__ fb,
    float* __restrict__ out, int B)
{
    extern __shared__ float sm[];
    float* sSeq  = sm + OFF_SEQ;   // [32][192]
    float* sQKV  = sm + OFF_QKV;   // [32][576]
    float* sSc   = sm + OFF_SC;
    float* sMu   = sm + OFF_MU;
    float* sRstd = sm + OFF_RSTD;
    float* sInv  = sm + OFF_INV;

    const int tid = threadIdx.x;
    const int fg  = tid % 48;      // feature quad index
    const int rg  = tid / 48;      // row group (0..3)
    const int f0  = fg * 4;
    const int r0  = blockIdx.x * RPB;

    // ---------- stage perc rows into sQKV rows (stride 576), compute p ----------
#pragma unroll
    for (int r = 0; r < RPB; r++) {
        int gr = r0 + r; if (gr >= B) gr = B - 1;
        sQKV[r * 576 + tid] = perc[(size_t)gr * D + tid];
    }
    __syncthreads();
    gemm4t<4, 0>(g_wt + T_WP + f0, D, D, bp, sQKV + rg * 4 * 576, 576,
                 sSeq + (rg * 8) * D + f0, 2 * D, f0);
    __syncthreads();

    // ---------- stage tech rows, compute t ----------
#pragma unroll
    for (int r = 0; r < RPB; r++) {
        int gr = r0 + r; if (gr >= B) gr = B - 1;
        sQKV[r * 576 + tid] = tech[(size_t)gr * D + tid];
    }
    __syncthreads();
    gemm4t<4, 0>(g_wt + T_WT + f0, D, D, bt, sQKV + rg * 4 * 576, 576,
                 sSeq + (rg * 8 + 1) * D + f0, 2 * D, f0);
    __syncthreads();

    // ---------- qkv = seq @ in_w^T + in_b  (3 passes) ----------
    for (int m = 0; m < 3; m++) {
        gemm4t<8, 0>(g_wt + T_IN + m * D + f0, 3 * D, D, in_b + m * D,
                     sSeq + rg * 8 * D, D,
                     sQKV + rg * 8 * 576 + m * D + f0, 576, f0);
    }
    __syncthreads();

    // ---------- attention scores: one 64-dot per thread ----------
    {
        const int r   = tid / 12;
        const int idx = tid % 12;
        const int h = idx >> 2, qt = (idx >> 1) & 1, kt = idx & 1;
        const float* q  = &sQKV[(2 * r + qt) * 576 + h * HD];
        const float* kk = &sQKV[(2 * r + kt) * 576 + D + h * HD];
        float s = 0.f;
#pragma unroll
        for (int d = 0; d < HD; d += 4) {
            float4 qa = ldf4(q + d), ka = ldf4(kk + d);
            s = fmaf(qa.x, ka.x, s);
            s = fmaf(qa.y, ka.y, s);
            s = fmaf(qa.z, ka.z, s);
            s = fmaf(qa.w, ka.w, s);
        }
        sSc[tid] = s * 0.125f;   // 1/sqrt(64)
    }
    __syncthreads();

    // ---------- softmax + ctx (overwrites q slots, cols [0,192)) ----------
    {
        const int h = tid >> 6;
#pragma unroll 2
        for (int r = 0; r < RPB; r++) {
            const float v0 = sQKV[(2 * r)     * 576 + 2 * D + tid];
            const float v1 = sQKV[(2 * r + 1) * 576 + 2 * D + tid];
            const float* sc = &sSc[r * 12 + h * 4];
            float ctx0, ctx1;
            {
                float s0 = sc[0], s1 = sc[1];
                float mx = fmaxf(s0, s1);
                float e0 = __expf(s0 - mx), e1 = __expf(s1 - mx);
                ctx0 = (e0 * v0 + e1 * v1) / (e0 + e1);
            }
            {
                float s0 = sc[2], s1 = sc[3];
                float mx = fmaxf(s0, s1);
                float e0 = __expf(s0 - mx), e1 = __expf(s1 - mx);
                ctx1 = (e0 * v0 + e1 * v1) / (e0 + e1);
            }
            sQKV[(2 * r)     * 576 + tid] = ctx0;
            sQKV[(2 * r + 1) * 576 + tid] = ctx1;
        }
    }
    __syncthreads();

    // ---------- attn out-proj, residual-add into sSeq ----------
    gemm4t<8, 2>(g_wt + T_OUT + f0, D, D, out_b, sQKV + rg * 8 * 576, 576,
                 sSeq + rg * 8 * D + f0, D, f0);
    __syncthreads();

    // ---------- LN1 ----------
    block_layernorm(sSeq, sMu, sRstd, ln1g, ln1b, tid);

    // ---------- FFN1: relu(x @ w1^T + b1) -> sQKV cols [0,384) ----------
    for (int m = 0; m < 2; m++) {
        gemm4t<8, 1>(g_wt + T_W1 + m * D + f0, 2 * D, D, b1 + m * D,
                     sSeq + rg * 8 * D, D,
                     sQKV + rg * 8 * 576 + m * D + f0, 576, f0);
    }
    __syncthreads();

    // ---------- FFN2 (K=384), residual-add into sSeq ----------
    gemm4t<8, 2>(g_wt + T_W2 + f0, D, 2 * D, b2, sQKV + rg * 8 * 576, 576,
                 sSeq + rg * 8 * D + f0, D, f0);
    __syncthreads();

    // ---------- LN2 ----------
    block_layernorm(sSeq, sMu, sRstd, ln2g, ln2b, tid);

    // ---------- pooled z into sSeq rows [0,16) ----------
#pragma unroll
    for (int r = 0; r < RPB; r++) {
        float z = 0.5f * (sSeq[(2 * r) * D + tid] + sSeq[(2 * r + 1) * D + tid]);
        sSeq[r * D + tid] = z;
    }
    __syncthreads();

    // ---------- classifier hidden -> sQKV rows [0,16) ----------
    gemm4t<4, 1>(g_wt + T_CW1 + f0, D, D, cb1, sSeq + rg * 4 * D, D,
                 sQKV + rg * 4 * 576 + f0, 576, f0);

    // ---------- fingerprint -> sQKV rows [16,32), 128 features ----------
    if (fg < 32) {
        gemm4t<4, 0>(g_wt + T_FW + f0, FPD, D, fb, sSeq + rg * 4 * D, D,
                     sQKV + (RPB + rg * 4) * 576 + f0, 576, f0);
    }
    __syncthreads();

    // ---------- logits + sigmoid ----------
    if (tid < 3 * RPB) {
        const int r = tid / 3, c = tid % 3;
        const float* y = &sQKV[r * 576];
        const float* w = cw2 + c * D;
        float s = cb2[c];
#pragma unroll
        for (int k = 0; k < D; k += 4) {
            float4 ya = ldf4(y + k), wa = ldf4(w + k);
            s = fmaf(ya.x, wa.x, s);
            s = fmaf(ya.y, wa.y, s);
            s = fmaf(ya.z, wa.z, s);
            s = fmaf(ya.w, wa.w, s);
        }
        const int gr = r0 + r;
        if (gr < B) out[(size_t)c * B + gr] = 1.f / (1.f + __expf(-s));
    }

    // ---------- fingerprint norm ----------
    if (tid < RPB) {
        const float* fpv = &sQKV[(RPB + tid) * 576];
        float ss = 0.f;
#pragma unroll 4
        for (int i = 0; i < FPD; i++) ss = fmaf(fpv[i], fpv[i], ss);
        sInv[tid] = 1.f / fmaxf(sqrtf(ss), 1e-12f);
    }
    __syncthreads();
    if (tid < FPD) {
#pragma unroll
        for (int r = 0; r < RPB; r++) {
            const int gr = r0 + r;
            if (gr < B)
                out[(size_t)3 * B + (size_t)gr * FPD + tid] =
                    sQKV[(RPB + r) * 576 + tid] * sInv[r];
        }
    }
}

extern "C" void kernel_launch(void* const* d_in, const int* in_sizes, int n_in,
                              void* d_out, int out_size)
{
    (void)n_in; (void)out_size;
    const float* perc = (const float*)d_in[0];
    const float* tech = (const float*)d_in[1];
    const float* Wp   = (const float*)d_in[2];
    const float* bp   = (const float*)d_in[3];
    const float* Wt   = (const float*)d_in[4];
    const float* bt   = (const float*)d_in[5];
    const float* in_w = (const float*)d_in[6];
    const float* in_b = (const float*)d_in[7];
    const float* outw = (const float*)d_in[8];
    const float* outb = (const float*)d_in[9];
    const float* w1   = (const float*)d_in[10];
    const float* b1   = (const float*)d_in[11];
    const float* w2   = (const float*)d_in[12];
    const float* b2   = (const float*)d_in[13];
    const float* ln1g = (const float*)d_in[14];
    const float* ln1b = (const float*)d_in[15];
    const float* ln2g = (const float*)d_in[16];
    const float* ln2b = (const float*)d_in[17];
    const float* cw1  = (const float*)d_in[18];
    const float* cb1  = (const float*)d_in[19];
    const float* cw2  = (const float*)d_in[20];
    const float* cb2  = (const float*)d_in[21];
    const float* fw   = (const float*)d_in[22];
    const float* fb   = (const float*)d_in[23];

    const int B = in_sizes[0] / D;
    const int grid = (B + RPB - 1) / RPB;

    // 1) transpose weights into g_wt (largest matrix 576*192 = 110592 elems)
    {
        dim3 g((110592 + 255) / 256, 8);
        transpose_weights<<<g, 256>>>(Wp, Wt, in_w, outw, w1, w2, cw1, fw);
    }

    // 2) main fused kernel
    cudaFuncSetAttribute(fusion_head_kernel,
                         cudaFuncAttributeMaxDynamicSharedMemorySize, SMEM_BYTES);
    fusion_head_kernel<<<grid, NT, SMEM_BYTES>>>(
        perc, tech, bp, bt, in_b, outb, b1, b2,
        ln1g, ln1b, ln2g, ln2b, cb1, cw2, cb2, fb,
        (float*)d_out, B);
}